// round 11
// baseline (speedup 1.0000x reference)
#include <cuda_runtime.h>
#include <cuda.h>
#include <cstdint>
#include <cstddef>
#include <cstring>

#define Bn 4096
#define Tn 200
#define Dn 128
#define Hn 16
#define NTHREADS 640
#define GRID 148
#define PANELB 25600            // bytes per k-panel (200 rows x 128 B)

// float offsets (within 1024B-aligned smem base)
#define OF_BUF0   0             // 25600 floats
#define OF_BUF1   25600         // 25600 floats
#define OF_UNION  51200         // 2560 floats: {sB 2048 | sq 128 | scpart 256} vs spart20
#define OF_SB     51200
#define OF_SQ     53248
#define OF_SCP    53376
#define OF_SC     53760         // 16
#define OF_SW2    53776         // 16
#define OF_SSC    53792         // 200
#define OF_SRED   53992         // 16
#define OF_MBAR   54008         // 4 floats = two 8B mbarriers
#define SMEM_FLOATS 54012
#define SMEM_BYTES (SMEM_FLOATS * 4 + 1024)

__device__ __forceinline__ uint32_t f2tf32(float x) {
    uint32_t u;
    asm("cvt.rna.tf32.f32 %0, %1;" : "=r"(u) : "f"(x));
    return u;
}

__device__ __forceinline__ void mma_tf32(float c[4], const uint32_t a[4],
                                         uint32_t b0, uint32_t b1) {
    asm volatile(
        "mma.sync.aligned.m16n8k8.row.col.f32.tf32.tf32.f32 "
        "{%0,%1,%2,%3}, {%4,%5,%6,%7}, {%8,%9}, {%0,%1,%2,%3};"
        : "+f"(c[0]), "+f"(c[1]), "+f"(c[2]), "+f"(c[3])
        : "r"(a[0]), "r"(a[1]), "r"(a[2]), "r"(a[3]), "r"(b0), "r"(b1));
}

__device__ __forceinline__ void mbar_wait(uint32_t mbar, int parity) {
    asm volatile(
        "{\n\t.reg .pred P;\n\t"
        "WLP_%=:\n\t"
        "mbarrier.try_wait.parity.acquire.cta.shared::cta.b64 P, [%0], %1, 0x989680;\n\t"
        "@P bra.uni WDN_%=;\n\t"
        "bra.uni WLP_%=;\n\t"
        "WDN_%=:\n\t}"
        :: "r"(mbar), "r"(parity) : "memory");
}

__device__ __forceinline__ void tma_tile(const CUtensorMap* tmap, uint32_t dst,
                                         uint32_t mbar, int batch) {
    asm volatile("mbarrier.arrive.expect_tx.shared.b64 _, [%0], %1;"
                 :: "r"(mbar), "r"(102400u) : "memory");
    #pragma unroll
    for (int p = 0; p < 4; ++p) {
        asm volatile(
            "cp.async.bulk.tensor.2d.shared::cta.global.tile.mbarrier::complete_tx::bytes "
            "[%0], [%1, {%2, %3}], [%4];"
            :: "r"(dst + p * PANELB), "l"(tmap),
               "r"(p * 32), "r"(batch * Tn), "r"(mbar)
            : "memory");
    }
}

// cp.async fallback: fill one tile in the SW128 HW layout (all threads)
__device__ __forceinline__ void ca_tile(uint32_t dstbase, const float* src, int tid) {
    const float4* fg = (const float4*)src;
    #pragma unroll
    for (int k = 0; k < 10; ++k) {
        int i = tid + k * NTHREADS;
        if (i < 6400) {
            int t = i >> 5, u = i & 31;
            uint32_t dst = dstbase + (u >> 3) * PANELB + t * 128
                         + (((u & 7) * 16) ^ ((t & 7) << 4));
            asm volatile("cp.async.cg.shared.global [%0], [%1], 16;\n"
                         :: "r"(dst), "l"(fg + i) : "memory");
        }
    }
    asm volatile("cp.async.commit_group;\n" ::: "memory");
}

__global__ void __launch_bounds__(NTHREADS, 1) din_kernel(
    const float* __restrict__ query,
    const float* __restrict__ facts,
    const int* __restrict__ mask,
    const float* __restrict__ W1,
    const float* __restrict__ b1,
    const float* __restrict__ W2,
    const float* __restrict__ b2,
    float* __restrict__ out,
    const __grid_constant__ CUtensorMap tmap,
    const int use_tma)
{
    extern __shared__ float smem_raw[];
    float* smem = (float*)(((uintptr_t)smem_raw + 1023) & ~(uintptr_t)1023);
    float* sB      = smem + OF_SB;
    float* sq      = smem + OF_SQ;
    float* scpart  = smem + OF_SCP;
    float* sc      = smem + OF_SC;
    float* sw2     = smem + OF_SW2;
    float* sscore  = smem + OF_SSC;
    float* sred    = smem + OF_SRED;
    float* spart20 = smem + OF_UNION;   // aliases sB/sq/scpart after score phase

    const int tid  = threadIdx.x;
    const int w    = tid >> 5;          // 20 warps
    const int lane = tid & 31;
    const int gid  = lane >> 2;
    const int tig  = lane & 3;
    const float b2v = b2[0];

    const uint32_t smem_u32 = (uint32_t)__cvta_generic_to_shared(smem);
    const uint32_t mb0 = smem_u32 + OF_MBAR * 4;
    const uint32_t mb1 = mb0 + 8;

    // ---- prologue ----
    if (use_tma) {
        if (tid == 0) {
            asm volatile("mbarrier.init.shared.b64 [%0], 1;" :: "r"(mb0) : "memory");
            asm volatile("mbarrier.init.shared.b64 [%0], 1;" :: "r"(mb1) : "memory");
            asm volatile("fence.proxy.async.shared::cta;" ::: "memory");
            tma_tile(&tmap, smem_u32 + OF_BUF0 * 4, mb0, blockIdx.x);
            tma_tile(&tmap, smem_u32 + OF_BUF1 * 4, mb1, blockIdx.x + GRID);
        }
    }
    if (tid < Hn) sw2[tid] = W2[tid];
    __syncthreads();   // mbar init visible to all waiters

    int ph0 = 0, ph1 = 0;
    int it = 0;
    for (int b = blockIdx.x; b < Bn; b += GRID, ++it) {
        const int cur = it & 1;
        char* sfb = (char*)(smem + (cur ? OF_BUF1 : OF_BUF0));

        if (!use_tma)   // fallback: synchronous-ish load of this tile
            ca_tile(smem_u32 + (cur ? OF_BUF1 : OF_BUF0) * 4,
                    facts + (size_t)b * (Tn * Dn), tid);

        if (tid < Dn) sq[tid] = query[(size_t)b * Dn + tid];
        __syncthreads();   // (1) sq visible; prev iter fully retired

        // ---- folded weights into sB (packed: one LDS.128 per ks per lane) ----
        #pragma unroll
        for (int k = 0; k < 4; ++k) {
            int i = tid + k * NTHREADS;
            if (i < Dn * Hn) {
                int d = i >> 4;
                int h = i & 15;
                float wf = W1[(128 + d) * Hn + h];
                float wd = W1[(256 + d) * Hn + h];
                float wm = W1[(384 + d) * Hn + h];
                uint32_t r = f2tf32((wf - wd) + sq[d] * wm);
                int ks = d >> 3, tg = d & 3, j = (d >> 2) & 1;
                int nt = h >> 3, gg = h & 7;
                sB[(((ks * 8 + gg) * 4 + tg) * 4) + nt * 2 + j] = __uint_as_float(r);
            }
        }
        if (tid < 256) {
            int h = tid & 15, chunk = tid >> 4;
            float acc = 0.f;
            #pragma unroll
            for (int j = 0; j < 8; ++j) {
                int d = chunk * 8 + j;
                acc += sq[d] * (W1[d * Hn + h] + W1[(256 + d) * Hn + h]);
            }
            scpart[tid] = acc;
        }
        __syncthreads();   // (2)
        if (tid < Hn) {
            float acc = b1[tid];
            #pragma unroll
            for (int k = 0; k < 16; ++k) acc += scpart[k * 16 + tid];
            sc[tid] = acc;
        }

        // ---- wait for this batch's tile ----
        if (use_tma) {
            if (cur) { mbar_wait(mb1, ph1); ph1 ^= 1; }
            else     { mbar_wait(mb0, ph0); ph0 ^= 1; }
        } else {
            asm volatile("cp.async.wait_group 0;\n" ::: "memory");
        }
        __syncthreads();   // (3) sc visible; everyone past the wait

        // ---- scores via tf32 MMA: warp w -> m-tile w (13 tiles, t=0..207) ----
        if (w < 13) {
            const int t0 = w * 16 + gid;
            const int t1 = t0 + 8;
            const int var0 = (t0 & 7) << 4, var1 = (t1 & 7) << 4;
            const int row0 = t0 * 128,      row1 = t1 * 128;
            const int tig4 = tig * 4;
            const float4* Bp = ((const float4*)sB) + gid * 4 + tig;

            int m0 = mask[(size_t)b * Tn + t0];
            int m1 = (t1 < Tn) ? mask[(size_t)b * Tn + t1] : 0;

            float c0a[4] = {0,0,0,0}, c0b[4] = {0,0,0,0};
            float c1a[4] = {0,0,0,0}, c1b[4] = {0,0,0,0};
            #pragma unroll
            for (int ks = 0; ks < 16; ks += 2) {
                int pb = (ks >> 2) * PANELB;
                int c  = (ks & 3) * 32 + tig4;
                uint32_t a[4];
                a[0] = __float_as_uint(*(const float*)(sfb + pb + row0 + ( c       ^ var0)));
                a[1] = __float_as_uint(*(const float*)(sfb + pb + row1 + ( c       ^ var1)));
                a[2] = __float_as_uint(*(const float*)(sfb + pb + row0 + ((c + 16) ^ var0)));
                a[3] = __float_as_uint(*(const float*)(sfb + pb + row1 + ((c + 16) ^ var1)));
                float4 bf = Bp[ks * 32];
                mma_tf32(c0a, a, __float_as_uint(bf.x), __float_as_uint(bf.y));
                mma_tf32(c1a, a, __float_as_uint(bf.z), __float_as_uint(bf.w));
                int pb2 = ((ks + 1) >> 2) * PANELB;
                int c2  = ((ks + 1) & 3) * 32 + tig4;
                uint32_t a2[4];
                a2[0] = __float_as_uint(*(const float*)(sfb + pb2 + row0 + ( c2       ^ var0)));
                a2[1] = __float_as_uint(*(const float*)(sfb + pb2 + row1 + ( c2       ^ var1)));
                a2[2] = __float_as_uint(*(const float*)(sfb + pb2 + row0 + ((c2 + 16) ^ var0)));
                a2[3] = __float_as_uint(*(const float*)(sfb + pb2 + row1 + ((c2 + 16) ^ var1)));
                float4 bg = Bp[(ks + 1) * 32];
                mma_tf32(c0b, a2, __float_as_uint(bg.x), __float_as_uint(bg.y));
                mma_tf32(c1b, a2, __float_as_uint(bg.z), __float_as_uint(bg.w));
            }
            float c0[4], c1[4];
            #pragma unroll
            for (int i = 0; i < 4; ++i) { c0[i] = c0a[i] + c0b[i]; c1[i] = c1a[i] + c1b[i]; }

            float part0 = 0.f, part1 = 0.f;
            #pragma unroll
            for (int nt = 0; nt < 2; ++nt) {
                int h0 = nt * 8 + 2 * tig;
                float scA = sc[h0],   w2A = sw2[h0];
                float scB = sc[h0+1], w2B = sw2[h0+1];
                const float* cc = nt ? c1 : c0;
                part0 += __fdividef(w2A, 1.0f + __expf(-(cc[0] + scA)));
                part0 += __fdividef(w2B, 1.0f + __expf(-(cc[1] + scB)));
                part1 += __fdividef(w2A, 1.0f + __expf(-(cc[2] + scA)));
                part1 += __fdividef(w2B, 1.0f + __expf(-(cc[3] + scB)));
            }
            part0 += __shfl_xor_sync(0xffffffffu, part0, 1);
            part0 += __shfl_xor_sync(0xffffffffu, part0, 2);
            part1 += __shfl_xor_sync(0xffffffffu, part1, 1);
            part1 += __shfl_xor_sync(0xffffffffu, part1, 2);

            float e0 = m0 ? __expf(b2v + part0) : 0.f;
            float e1 = (t1 < Tn && m1) ? __expf(b2v + part1) : 0.f;
            if (tig == 0) {
                sscore[t0] = e0;
                if (t1 < Tn) sscore[t1] = e1;
            }
            float es = e0 + e1;
            es += __shfl_xor_sync(0xffffffffu, es, 4);
            es += __shfl_xor_sync(0xffffffffu, es, 8);
            es += __shfl_xor_sync(0xffffffffu, es, 16);
            if (lane == 0) sred[w] = es;
        }
        __syncthreads();   // (4) buf[cur] consumed; sB dead -> spart20

        // prefetch batch b+2*GRID into the buffer just freed (TMA path only)
        if (use_tma && tid == 0 && b + 2 * GRID < Bn) {
            uint32_t dst = smem_u32 + (cur ? OF_BUF1 : OF_BUF0) * 4;
            tma_tile(&tmap, dst, cur ? mb1 : mb0, b + 2 * GRID);
        }
        if (tid == 32) {
            float ssum = 0.f;
            #pragma unroll
            for (int k = 0; k < 13; ++k) ssum += sred[k];
            sred[15] = 1.0f / ssum;
        }

        // ---- weighted sum from GLOBAL (L2-hot): warp w -> t = w + 20i ----
        {
            const float4* fb = (const float4*)(facts + (size_t)b * (Tn * Dn));
            float4 acc = make_float4(0.f, 0.f, 0.f, 0.f);
            #pragma unroll
            for (int i = 0; i < 10; ++i) {
                int t = w + 20 * i;
                float a0 = sscore[t];
                float4 f4 = fb[t * 32 + lane];
                acc.x += a0 * f4.x; acc.y += a0 * f4.y;
                acc.z += a0 * f4.z; acc.w += a0 * f4.w;
            }
            ((float4*)spart20)[w * 32 + lane] = acc;
        }
        __syncthreads();   // (5)

        if (tid < Dn) {
            const float inv = sred[15];
            float acc = 0.f;
            #pragma unroll
            for (int s = 0; s < 20; ++s) acc += spart20[s * Dn + tid];
            out[(size_t)b * Dn + tid] = acc * inv;
        }
        // next iter's barrier (1) protects spart20/sred before reuse
    }
}

typedef CUresult (*PFN_encodeTiled_t)(
    CUtensorMap*, CUtensorMapDataType, cuuint32_t, void*,
    const cuuint64_t*, const cuuint64_t*, const cuuint32_t*, const cuuint32_t*,
    CUtensorMapInterleave, CUtensorMapSwizzle, CUtensorMapL2promotion,
    CUtensorMapFloatOOBfill);

extern "C" void kernel_launch(void* const* d_in, const int* in_sizes, int n_in,
                              void* d_out, int out_size) {
    const float* query = (const float*)d_in[0];
    const float* facts = (const float*)d_in[1];
    const int*   mask  = (const int*)d_in[2];
    const float* W1    = (const float*)d_in[3];
    const float* b1    = (const float*)d_in[4];
    const float* W2    = (const float*)d_in[5];
    const float* b2    = (const float*)d_in[6];
    float*       out   = (float*)d_out;

    int B = in_sizes[0] / Dn;   // 4096

    CUtensorMap tmap;
    memset(&tmap, 0, sizeof(tmap));
    int use_tma = 0;

    PFN_encodeTiled_t fn = nullptr;
    cudaDriverEntryPointQueryResult qr = cudaDriverEntryPointSymbolNotFound;
#if CUDART_VERSION >= 12050
    cudaGetDriverEntryPointByVersion("cuTensorMapEncodeTiled", (void**)&fn, 12000,
                                     cudaEnableDefault, &qr);
#else
    cudaGetDriverEntryPoint("cuTensorMapEncodeTiled", (void**)&fn,
                            cudaEnableDefault, &qr);
#endif
    if (qr == cudaDriverEntryPointSuccess && fn) {
        cuuint64_t gdim[2]    = {(cuuint64_t)Dn, (cuuint64_t)B * Tn};
        cuuint64_t gstride[1] = {(cuuint64_t)Dn * 4};
        cuuint32_t box[2]     = {32, 200};
        cuuint32_t estride[2] = {1, 1};
        CUresult r = fn(&tmap, CU_TENSOR_MAP_DATA_TYPE_FLOAT32, 2, (void*)facts,
                        gdim, gstride, box, estride,
                        CU_TENSOR_MAP_INTERLEAVE_NONE, CU_TENSOR_MAP_SWIZZLE_128B,
                        CU_TENSOR_MAP_L2_PROMOTION_L2_128B,
                        CU_TENSOR_MAP_FLOAT_OOB_FILL_NONE);
        if (r == CUDA_SUCCESS) use_tma = 1;
    }

    cudaFuncSetAttribute(din_kernel, cudaFuncAttributeMaxDynamicSharedMemorySize,
                         SMEM_BYTES);
    din_kernel<<<GRID, NTHREADS, SMEM_BYTES>>>(query, facts, mask, W1, b1, W2, b2,
                                               out, tmap, use_tma);
}